// round 1
// baseline (speedup 1.0000x reference)
#include <cuda_runtime.h>

#define DIN 512
#define DH  256
#define GNUM 128
#define NMAX 20000

// ---- scratch (static __device__ globals; no allocation allowed) ----
__device__ float g_y[NMAX * DH];     // y = (A @ W) * dinv[row]
__device__ float g_acc[NMAX * DH];   // scatter accumulator (init = y, covers self loop)
__device__ float g_h[NMAX * DH];     // layer output h = relu(acc*dinv + b)
__device__ float g_deg[NMAX];
__device__ float g_dinv[NMAX];
__device__ float g_pool[GNUM * DH];
__device__ float g_cnt[GNUM];

// ---------------- degree / dinv ----------------
__global__ void k_init_deg(int N) {
    int i = blockIdx.x * blockDim.x + threadIdx.x;
    if (i < N) g_deg[i] = 1.0f;   // self loop
}

__global__ void k_deg_acc(const int* __restrict__ dst, int E) {
    int e = blockIdx.x * blockDim.x + threadIdx.x;
    if (e < E) atomicAdd(&g_deg[dst[e]], 1.0f);
}

__global__ void k_dinv(int N) {
    int i = blockIdx.x * blockDim.x + threadIdx.x;
    if (i < N) g_dinv[i] = rsqrtf(g_deg[i]);
}

// ---------------- SGEMM: y = (A @ W) * dinv[row]; acc = y ----------------
// BM=128, BN=128, BK=16, 256 threads, 8x8 microtile. W is [K, 256] row-major.
template<int K, bool FROM_H>
__global__ void __launch_bounds__(256)
k_gemm_scaled(const float* __restrict__ Ax, const float* __restrict__ W, int M)
{
    const float* __restrict__ A = FROM_H ? (const float*)g_h : Ax;

    __shared__ float As[16][132];   // transposed A tile, 132*4=528 bytes/row (16B-aligned)
    __shared__ float Bs[16][128];

    const int rowBase = blockIdx.x * 128;
    const int colBase = blockIdx.y * 128;
    const int tid = threadIdx.x;
    const int ty = tid >> 4;        // 0..15
    const int tx = tid & 15;        // 0..15

    float acc[8][8];
    #pragma unroll
    for (int i = 0; i < 8; i++)
        #pragma unroll
        for (int j = 0; j < 8; j++) acc[i][j] = 0.0f;

    for (int k0 = 0; k0 < K; k0 += 16) {
        // load A tile: 128 rows x 16 cols = 512 float4, 2 per thread
        #pragma unroll
        for (int i = 0; i < 2; i++) {
            int idx = tid + i * 256;
            int r  = idx >> 2;            // 0..127
            int c4 = (idx & 3) << 2;      // 0,4,8,12
            int gr = rowBase + r;
            float4 v = make_float4(0.f, 0.f, 0.f, 0.f);
            if (gr < M) v = *(const float4*)(A + (size_t)gr * K + k0 + c4);
            As[c4 + 0][r] = v.x;
            As[c4 + 1][r] = v.y;
            As[c4 + 2][r] = v.z;
            As[c4 + 3][r] = v.w;
        }
        // load W tile: 16 rows x 128 cols = 512 float4, 2 per thread
        #pragma unroll
        for (int i = 0; i < 2; i++) {
            int idx = tid + i * 256;
            int r  = idx >> 5;            // 0..15
            int c4 = (idx & 31) << 2;     // 0..124
            float4 v = *(const float4*)(W + (size_t)(k0 + r) * DH + colBase + c4);
            *(float4*)&Bs[r][c4] = v;
        }
        __syncthreads();

        #pragma unroll
        for (int k = 0; k < 16; k++) {
            float a[8], b[8];
            *(float4*)&a[0] = *(const float4*)&As[k][ty * 8];
            *(float4*)&a[4] = *(const float4*)&As[k][ty * 8 + 4];
            *(float4*)&b[0] = *(const float4*)&Bs[k][tx * 8];
            *(float4*)&b[4] = *(const float4*)&Bs[k][tx * 8 + 4];
            #pragma unroll
            for (int i = 0; i < 8; i++)
                #pragma unroll
                for (int j = 0; j < 8; j++)
                    acc[i][j] = fmaf(a[i], b[j], acc[i][j]);
        }
        __syncthreads();
    }

    // epilogue: scale by dinv[row], write y and acc (acc init = y covers self loop)
    #pragma unroll
    for (int i = 0; i < 8; i++) {
        int gr = rowBase + ty * 8 + i;
        if (gr >= M) continue;
        float s = g_dinv[gr];
        #pragma unroll
        for (int j = 0; j < 8; j += 4) {
            float4 v;
            v.x = acc[i][j + 0] * s;
            v.y = acc[i][j + 1] * s;
            v.z = acc[i][j + 2] * s;
            v.w = acc[i][j + 3] * s;
            size_t off = (size_t)gr * DH + colBase + tx * 8 + j;
            *(float4*)&g_y[off]   = v;
            *(float4*)&g_acc[off] = v;
        }
    }
}

// ---------------- edge scatter: acc[dst] += y[src] ----------------
// 64 threads per edge, each a float4 (256 floats/row)
__global__ void k_scatter(const int* __restrict__ src, const int* __restrict__ dst, int E)
{
    int t = blockIdx.x * blockDim.x + threadIdx.x;
    int e = t >> 6;
    if (e >= E) return;
    int c = (t & 63) << 2;
    int s = src[e];
    int d = dst[e];
    float4 v = *(const float4*)(g_y + (size_t)s * DH + c);
    float* o = g_acc + (size_t)d * DH + c;
    atomicAdd(o + 0, v.x);
    atomicAdd(o + 1, v.y);
    atomicAdd(o + 2, v.z);
    atomicAdd(o + 3, v.w);
}

// ---------------- h = relu(acc * dinv + b) ----------------
__global__ void k_post_relu(const float* __restrict__ bias, int N)
{
    int t = blockIdx.x * blockDim.x + threadIdx.x;
    int i = t >> 6;
    if (i >= N) return;
    int c = (t & 63) << 2;
    float s = g_dinv[i];
    float4 v = *(const float4*)(g_acc + (size_t)i * DH + c);
    float4 b = *(const float4*)(bias + c);
    v.x = fmaxf(fmaf(v.x, s, b.x), 0.f);
    v.y = fmaxf(fmaf(v.y, s, b.y), 0.f);
    v.z = fmaxf(fmaf(v.z, s, b.z), 0.f);
    v.w = fmaxf(fmaf(v.w, s, b.w), 0.f);
    *(float4*)(g_h + (size_t)i * DH + c) = v;
}

// ---------------- pooling ----------------
__global__ void k_pool_init() {
    int t = blockIdx.x * blockDim.x + threadIdx.x;
    if (t < GNUM * DH) g_pool[t] = 0.f;
    if (t < GNUM) g_cnt[t] = 0.f;
}

__global__ void k_pool_acc(const int* __restrict__ batch, int N)
{
    int t = blockIdx.x * blockDim.x + threadIdx.x;
    int i = t >> 6;
    if (i >= N) return;
    int c = (t & 63) << 2;
    int g = batch[i];
    float4 v = *(const float4*)(g_h + (size_t)i * DH + c);
    float* o = g_pool + (size_t)g * DH + c;
    atomicAdd(o + 0, v.x);
    atomicAdd(o + 1, v.y);
    atomicAdd(o + 2, v.z);
    atomicAdd(o + 3, v.w);
    if (c == 0) atomicAdd(&g_cnt[g], 1.f);
}

// ---------------- final FC: out[g] = dot(pool[g]/max(cnt,1), w_fc) + b_fc ----------------
__global__ void k_fc(const float* __restrict__ wfc, const float* __restrict__ bfc,
                     float* __restrict__ out)
{
    int w = (blockIdx.x * blockDim.x + threadIdx.x) >> 5;
    int lane = threadIdx.x & 31;
    if (w >= GNUM) return;
    float sum = 0.f;
    #pragma unroll
    for (int j = lane; j < DH; j += 32)
        sum += g_pool[w * DH + j] * wfc[j];
    #pragma unroll
    for (int o = 16; o; o >>= 1)
        sum += __shfl_xor_sync(0xffffffffu, sum, o);
    if (lane == 0)
        out[w] = sum / fmaxf(g_cnt[w], 1.f) + bfc[0];
}

// ---------------- launch ----------------
extern "C" void kernel_launch(void* const* d_in, const int* in_sizes, int n_in,
                              void* d_out, int out_size)
{
    const float* x     = (const float*)d_in[0];
    const int*   ei    = (const int*)  d_in[1];
    const int*   batch = (const int*)  d_in[2];
    const float* W1    = (const float*)d_in[3];
    const float* b1    = (const float*)d_in[4];
    const float* W2    = (const float*)d_in[5];
    const float* b2    = (const float*)d_in[6];
    const float* wfc   = (const float*)d_in[7];
    const float* bfc   = (const float*)d_in[8];
    float* out = (float*)d_out;

    const int N = in_sizes[2];        // 20000
    const int E = in_sizes[1] / 2;    // 320000
    const int* src = ei;
    const int* dst = ei + E;

    // degree + dinv
    k_init_deg<<<(N + 255) / 256, 256>>>(N);
    k_deg_acc <<<(E + 255) / 256, 256>>>(dst, E);
    k_dinv    <<<(N + 255) / 256, 256>>>(N);

    dim3 gemm_grid((N + 127) / 128, DH / 128);
    int  sc_blocks   = (int)(((long long)E * 64 + 255) / 256);
    int  post_blocks = (int)(((long long)N * 64 + 255) / 256);

    // layer 1
    k_gemm_scaled<DIN, false><<<gemm_grid, 256>>>(x, W1, N);
    k_scatter  <<<sc_blocks, 256>>>(src, dst, E);
    k_post_relu<<<post_blocks, 256>>>(b1, N);

    // layer 2
    k_gemm_scaled<DH, true><<<gemm_grid, 256>>>(x /*unused*/, W2, N);
    k_scatter  <<<sc_blocks, 256>>>(src, dst, E);
    k_post_relu<<<post_blocks, 256>>>(b2, N);

    // pool + fc
    k_pool_init<<<(GNUM * DH + 255) / 256, 256>>>();
    k_pool_acc <<<post_blocks, 256>>>(batch, N);
    k_fc       <<<GNUM * 32 / 128, 128>>>(wfc, bfc, out);
}

// round 2
// speedup vs baseline: 1.7901x; 1.7901x over previous
#include <cuda_runtime.h>

#define DIN 512
#define DH  256
#define GNUM 128
#define NMAX 20000
#define EMAX 320000

// ---- scratch (static __device__ globals; no allocation allowed) ----
__device__ float g_y[NMAX * DH];     // y = (A @ W) * dinv[row]
__device__ float g_h[NMAX * DH];     // layer-1 output h = relu(...)
__device__ float g_deg[NMAX];        // 1 + in-degree
__device__ float g_dinv[NMAX];
__device__ int   g_off[NMAX];        // CSR offsets (exclusive scan of indeg)
__device__ int   g_cursor[NMAX];
__device__ int   g_esrc[EMAX];       // CSR: src node per incoming edge, grouped by dst
__device__ float g_pool[GNUM * DH];
__device__ float g_cnt[GNUM];

// ---------------- init / degree / dinv ----------------
__global__ void k_init_misc() {
    int t = blockIdx.x * blockDim.x + threadIdx.x;
    if (t < GNUM * DH) g_pool[t] = 0.f;
    if (t < GNUM) g_cnt[t] = 0.f;
    if (t < NMAX) g_deg[t] = 1.0f;   // self loop
}

__global__ void k_deg_acc(const int* __restrict__ dst, int E) {
    int e = blockIdx.x * blockDim.x + threadIdx.x;
    if (e < E) atomicAdd(&g_deg[dst[e]], 1.0f);
}

__global__ void k_dinv_cnt(const int* __restrict__ batch, int N) {
    int i = blockIdx.x * blockDim.x + threadIdx.x;
    if (i < N) {
        g_dinv[i] = rsqrtf(g_deg[i]);
        atomicAdd(&g_cnt[batch[i]], 1.0f);
    }
}

// ---------------- CSR build: exclusive scan of indeg, then edge fill ----------------
__global__ void __launch_bounds__(1024) k_scan(int N) {
    __shared__ int wsum[32];
    const int tid = threadIdx.x;
    const int per = (N + 1023) >> 10;
    const int s = tid * per;
    const int e = min(s + per, N);
    int sum = 0;
    for (int i = s; i < e; i++) sum += (int)g_deg[i] - 1;

    const int lane = tid & 31, w = tid >> 5;
    int v = sum;
    #pragma unroll
    for (int o = 1; o < 32; o <<= 1) {
        int t = __shfl_up_sync(0xffffffffu, v, o);
        if (lane >= o) v += t;
    }
    if (lane == 31) wsum[w] = v;
    __syncthreads();
    if (w == 0) {
        int x = wsum[lane];
        #pragma unroll
        for (int o = 1; o < 32; o <<= 1) {
            int t = __shfl_up_sync(0xffffffffu, x, o);
            if (lane >= o) x += t;
        }
        wsum[lane] = x;
    }
    __syncthreads();
    int run = v - sum + (w ? wsum[w - 1] : 0);   // exclusive prefix for this thread
    for (int i = s; i < e; i++) {
        g_off[i] = run;
        g_cursor[i] = 0;
        run += (int)g_deg[i] - 1;
    }
}

__global__ void k_fill(const int* __restrict__ src, const int* __restrict__ dst, int E) {
    int e = blockIdx.x * blockDim.x + threadIdx.x;
    if (e >= E) return;
    int d = dst[e];
    int pos = g_off[d] + atomicAdd(&g_cursor[d], 1);
    g_esrc[pos] = src[e];
}

// ---------------- SGEMM (double-buffered): g_y = (A @ W) * dinv[row] ----------------
// BM=128, BN=128, BK=16, 256 threads, 8x8 microtile, 2 CTAs/SM.
template<int K, bool FROM_H>
__global__ void __launch_bounds__(256, 2)
k_gemm(const float* __restrict__ Ax, const float* __restrict__ W, int M)
{
    const float* __restrict__ A = FROM_H ? (const float*)g_h : Ax;

    __shared__ float As[2][16][132];
    __shared__ float Bs[2][16][128];

    const int rowBase = blockIdx.x * 128;
    const int colBase = blockIdx.y * 128;
    const int tid = threadIdx.x;
    const int ty = tid >> 4;        // 0..15
    const int tx = tid & 15;        // 0..15

    const int ar  = tid >> 2;       // 0..63 (+64 for i=1)
    const int ac4 = (tid & 3) << 2; // 0,4,8,12
    const int br  = tid >> 5;       // 0..7  (+8 for i=1)
    const int bc4 = (tid & 31) << 2;

    float4 ra[2], rb[2];

    auto ldg = [&](int k0) {
        #pragma unroll
        for (int i = 0; i < 2; i++) {
            int gr = rowBase + ar + i * 64;
            ra[i] = (gr < M) ? *(const float4*)(A + (size_t)gr * K + k0 + ac4)
                             : make_float4(0.f, 0.f, 0.f, 0.f);
            rb[i] = *(const float4*)(W + (size_t)(k0 + br + i * 8) * DH + colBase + bc4);
        }
    };
    auto sts = [&](int buf) {
        #pragma unroll
        for (int i = 0; i < 2; i++) {
            int r = ar + i * 64;
            As[buf][ac4 + 0][r] = ra[i].x;
            As[buf][ac4 + 1][r] = ra[i].y;
            As[buf][ac4 + 2][r] = ra[i].z;
            As[buf][ac4 + 3][r] = ra[i].w;
            *(float4*)&Bs[buf][br + i * 8][bc4] = rb[i];
        }
    };

    float acc[8][8];
    #pragma unroll
    for (int i = 0; i < 8; i++)
        #pragma unroll
        for (int j = 0; j < 8; j++) acc[i][j] = 0.0f;

    ldg(0);
    sts(0);
    __syncthreads();

    int buf = 0;
    for (int k0 = 16; k0 <= K; k0 += 16) {
        if (k0 < K) ldg(k0);
        #pragma unroll
        for (int k = 0; k < 16; k++) {
            float a[8], b[8];
            *(float4*)&a[0] = *(const float4*)&As[buf][k][ty * 8];
            *(float4*)&a[4] = *(const float4*)&As[buf][k][ty * 8 + 4];
            *(float4*)&b[0] = *(const float4*)&Bs[buf][k][tx * 8];
            *(float4*)&b[4] = *(const float4*)&Bs[buf][k][tx * 8 + 4];
            #pragma unroll
            for (int i = 0; i < 8; i++)
                #pragma unroll
                for (int j = 0; j < 8; j++)
                    acc[i][j] = fmaf(a[i], b[j], acc[i][j]);
        }
        if (k0 < K) sts(buf ^ 1);
        __syncthreads();
        buf ^= 1;
    }

    // epilogue: scale by dinv[row], write g_y
    #pragma unroll
    for (int i = 0; i < 8; i++) {
        int gr = rowBase + ty * 8 + i;
        if (gr >= M) continue;
        float s = g_dinv[gr];
        #pragma unroll
        for (int j = 0; j < 8; j += 4) {
            float4 v;
            v.x = acc[i][j + 0] * s;
            v.y = acc[i][j + 1] * s;
            v.z = acc[i][j + 2] * s;
            v.w = acc[i][j + 3] * s;
            *(float4*)&g_y[(size_t)gr * DH + colBase + tx * 8 + j] = v;
        }
    }
}

// ---------------- CSR gather: acc = y[node] + sum(y[src]); h = relu(acc*dinv + b)
// 64 threads (float4 each) per node, 4 nodes per 256-thread block.
// LAYER2: fuse mean-pool accumulation instead of writing g_h.
template<bool LAYER2>
__global__ void __launch_bounds__(256)
k_gather(const int* __restrict__ batch, const float* __restrict__ bias, int N)
{
    int node = blockIdx.x * 4 + (threadIdx.x >> 6);
    if (node >= N) return;
    int c = (threadIdx.x & 63) << 2;

    float4 acc = *(const float4*)(g_y + (size_t)node * DH + c);  // self loop
    const int beg = g_off[node];
    const int cnt = (int)g_deg[node] - 1;
    #pragma unroll 4
    for (int j = 0; j < cnt; j++) {
        int s = g_esrc[beg + j];
        float4 v = *(const float4*)(g_y + (size_t)s * DH + c);
        acc.x += v.x; acc.y += v.y; acc.z += v.z; acc.w += v.w;
    }

    float dv = g_dinv[node];
    float4 b = *(const float4*)(bias + c);
    float4 r;
    r.x = fmaxf(fmaf(acc.x, dv, b.x), 0.f);
    r.y = fmaxf(fmaf(acc.y, dv, b.y), 0.f);
    r.z = fmaxf(fmaf(acc.z, dv, b.z), 0.f);
    r.w = fmaxf(fmaf(acc.w, dv, b.w), 0.f);

    if (!LAYER2) {
        *(float4*)(g_h + (size_t)node * DH + c) = r;
    } else {
        int g = batch[node];
        float* o = g_pool + (size_t)g * DH + c;
        atomicAdd(o + 0, r.x);
        atomicAdd(o + 1, r.y);
        atomicAdd(o + 2, r.z);
        atomicAdd(o + 3, r.w);
    }
}

// ---------------- final FC ----------------
__global__ void k_fc(const float* __restrict__ wfc, const float* __restrict__ bfc,
                     float* __restrict__ out)
{
    int w = (blockIdx.x * blockDim.x + threadIdx.x) >> 5;
    int lane = threadIdx.x & 31;
    if (w >= GNUM) return;
    float sum = 0.f;
    #pragma unroll
    for (int j = lane; j < DH; j += 32)
        sum += g_pool[w * DH + j] * wfc[j];
    #pragma unroll
    for (int o = 16; o; o >>= 1)
        sum += __shfl_xor_sync(0xffffffffu, sum, o);
    if (lane == 0)
        out[w] = sum / fmaxf(g_cnt[w], 1.f) + bfc[0];
}

// ---------------- launch ----------------
extern "C" void kernel_launch(void* const* d_in, const int* in_sizes, int n_in,
                              void* d_out, int out_size)
{
    const float* x     = (const float*)d_in[0];
    const int*   ei    = (const int*)  d_in[1];
    const int*   batch = (const int*)  d_in[2];
    const float* W1    = (const float*)d_in[3];
    const float* b1    = (const float*)d_in[4];
    const float* W2    = (const float*)d_in[5];
    const float* b2    = (const float*)d_in[6];
    const float* wfc   = (const float*)d_in[7];
    const float* bfc   = (const float*)d_in[8];
    float* out = (float*)d_out;

    const int N = in_sizes[2];        // 20000
    const int E = in_sizes[1] / 2;    // 320000
    const int* src = ei;
    const int* dst = ei + E;

    // prep: degree, dinv, group counts, CSR
    k_init_misc<<<(GNUM * DH + NMAX + 255) / 256, 256>>>();
    k_deg_acc  <<<(E + 255) / 256, 256>>>(dst, E);
    k_dinv_cnt <<<(N + 255) / 256, 256>>>(batch, N);
    k_scan     <<<1, 1024>>>(N);
    k_fill     <<<(E + 255) / 256, 256>>>(src, dst, E);

    dim3 gemm_grid((N + 127) / 128, DH / 128);
    int  gat_blocks = (N + 3) / 4;

    // layer 1
    k_gemm<DIN, false><<<gemm_grid, 256>>>(x, W1, N);
    k_gather<false><<<gat_blocks, 256>>>(batch, b1, N);

    // layer 2
    k_gemm<DH, true><<<gemm_grid, 256>>>(x /*unused*/, W2, N);
    k_gather<true><<<gat_blocks, 256>>>(batch, b2, N);

    // fc
    k_fc<<<GNUM * 32 / 128, 128>>>(wfc, bfc, out);
}

// round 3
// speedup vs baseline: 2.5052x; 1.3995x over previous
#include <cuda_runtime.h>

#define DIN 512
#define DH  256
#define GNUM 128
#define NMAX 20000
#define EMAX 320000
#define NBLK_MAX 256    // ceil(NMAX/128) = 157

// ---- scratch (static __device__ globals; no allocation allowed) ----
__device__ float g_y[NMAX * DH];     // y = (A @ W) * dinv[row]
__device__ float g_h[NMAX * DH];     // layer-1 output h = relu(...)
__device__ float g_deg[NMAX];        // 1 + in-degree
__device__ float g_dinv[NMAX];
__device__ int   g_off[NMAX];        // CSR offsets (exclusive scan of indeg)
__device__ int   g_cursor[NMAX];
__device__ int   g_esrc[EMAX];       // CSR: src node per incoming edge, grouped by dst
__device__ int   g_bsum[NBLK_MAX];
__device__ int   g_bpre[NBLK_MAX];
__device__ float g_pool[GNUM * DH];
__device__ float g_cnt[GNUM];

// ---------------- init / degree / dinv ----------------
__global__ void k_init_misc() {
    int t = blockIdx.x * blockDim.x + threadIdx.x;
    if (t < GNUM * DH) g_pool[t] = 0.f;
    if (t < GNUM) g_cnt[t] = 0.f;
    if (t < NMAX) g_deg[t] = 1.0f;   // self loop
}

__global__ void k_deg_acc(const int* __restrict__ dst, int E) {
    int e = blockIdx.x * blockDim.x + threadIdx.x;
    if (e < E) atomicAdd(&g_deg[dst[e]], 1.0f);
}

__global__ void k_dinv_cnt(const int* __restrict__ batch, int N) {
    int i = blockIdx.x * blockDim.x + threadIdx.x;
    if (i < N) {
        g_dinv[i] = rsqrtf(g_deg[i]);
        atomicAdd(&g_cnt[batch[i]], 1.0f);
    }
}

// ---------------- hierarchical exclusive scan of indegrees ----------------
// pass 1: per-block (128 nodes) sums
__global__ void __launch_bounds__(128) k_scan_part(int N) {
    __shared__ int ws[4];
    int i = blockIdx.x * 128 + threadIdx.x;
    int v = (i < N) ? (int)g_deg[i] - 1 : 0;
    int s = v;
    #pragma unroll
    for (int o = 16; o; o >>= 1) s += __shfl_xor_sync(0xffffffffu, s, o);
    if ((threadIdx.x & 31) == 0) ws[threadIdx.x >> 5] = s;
    __syncthreads();
    if (threadIdx.x == 0) g_bsum[blockIdx.x] = ws[0] + ws[1] + ws[2] + ws[3];
}

// pass 2: single block scans the (<=256) block sums -> exclusive
__global__ void __launch_bounds__(256) k_scan_tops(int nblk) {
    __shared__ int ws[8];
    int tid = threadIdx.x;
    int v = (tid < nblk) ? g_bsum[tid] : 0;
    int lane = tid & 31, w = tid >> 5;
    int inc = v;
    #pragma unroll
    for (int o = 1; o < 32; o <<= 1) {
        int t = __shfl_up_sync(0xffffffffu, inc, o);
        if (lane >= o) inc += t;
    }
    if (lane == 31) ws[w] = inc;
    __syncthreads();
    if (w == 0 && lane < 8) {
        int x = ws[lane];
        #pragma unroll
        for (int o = 1; o < 8; o <<= 1) {
            int t = __shfl_up_sync(0xffu, x, o);
            if (lane >= o) x += t;
        }
        ws[lane] = x;
    }
    __syncthreads();
    int excl = inc - v + (w ? ws[w - 1] : 0);
    if (tid < nblk) g_bpre[tid] = excl;
}

// pass 3: per-block exclusive scan + block prefix -> g_off
__global__ void __launch_bounds__(128) k_scan_off(int N) {
    __shared__ int ws[4];
    int i = blockIdx.x * 128 + threadIdx.x;
    int v = (i < N) ? (int)g_deg[i] - 1 : 0;
    int lane = threadIdx.x & 31, w = threadIdx.x >> 5;
    int inc = v;
    #pragma unroll
    for (int o = 1; o < 32; o <<= 1) {
        int t = __shfl_up_sync(0xffffffffu, inc, o);
        if (lane >= o) inc += t;
    }
    if (lane == 31) ws[w] = inc;
    __syncthreads();
    int base = g_bpre[blockIdx.x];
    if (w == 0 && lane < 4) {
        int x = ws[lane];
        #pragma unroll
        for (int o = 1; o < 4; o <<= 1) {
            int t = __shfl_up_sync(0xfu, x, o);
            if (lane >= o) x += t;
        }
        ws[lane] = x;
    }
    __syncthreads();
    if (i < N) {
        int excl = inc - v + (w ? ws[w - 1] : 0);
        g_off[i] = base + excl;
        g_cursor[i] = 0;
    }
}

__global__ void k_fill(const int* __restrict__ src, const int* __restrict__ dst, int E) {
    int e = blockIdx.x * blockDim.x + threadIdx.x;
    if (e >= E) return;
    int d = dst[e];
    int pos = g_off[d] + atomicAdd(&g_cursor[d], 1);
    g_esrc[pos] = src[e];
}

// ---------------- SGEMM (double-buffered): g_y = (A @ W) * dinv[row] ----------------
// BM=160, BN=128, BK=16, 256 threads, 10x8 microtile, 2 CTAs/SM.
// Grid = (125, 2) = 250 CTAs -> single wave on 148 SMs at occ 2.
template<int K, bool FROM_H>
__global__ void __launch_bounds__(256, 2)
k_gemm(const float* __restrict__ Ax, const float* __restrict__ W, int M)
{
    const float* __restrict__ A = FROM_H ? (const float*)g_h : Ax;

    __shared__ float As[2][16][164];   // [k][row], padded
    __shared__ float Bs[2][16][128];

    const int rowBase = blockIdx.x * 160;
    const int colBase = blockIdx.y * 128;
    const int tid = threadIdx.x;
    const int ty = tid >> 4;        // 0..15 -> rows ty*10..ty*10+9
    const int tx = tid & 15;        // 0..15 -> cols tx*8..tx*8+7

    // A tile: 160 rows x 16 cols = 640 float4; threads load idx = tid, tid+256, tid+512(<640)
    const int br  = tid >> 5;       // 0..7 (+8)
    const int bc4 = (tid & 31) << 2;

    float4 ra[3], rb[2];

    auto ldg = [&](int k0) {
        #pragma unroll
        for (int i = 0; i < 3; i++) {
            int idx = tid + i * 256;
            if (idx < 640) {
                int r  = idx >> 2;
                int c4 = (idx & 3) << 2;
                int gr = rowBase + r;
                ra[i] = (gr < M) ? *(const float4*)(A + (size_t)gr * K + k0 + c4)
                                 : make_float4(0.f, 0.f, 0.f, 0.f);
            }
        }
        #pragma unroll
        for (int i = 0; i < 2; i++)
            rb[i] = *(const float4*)(W + (size_t)(k0 + br + i * 8) * DH + colBase + bc4);
    };
    auto sts = [&](int buf) {
        #pragma unroll
        for (int i = 0; i < 3; i++) {
            int idx = tid + i * 256;
            if (idx < 640) {
                int r  = idx >> 2;
                int c4 = (idx & 3) << 2;
                As[buf][c4 + 0][r] = ra[i].x;
                As[buf][c4 + 1][r] = ra[i].y;
                As[buf][c4 + 2][r] = ra[i].z;
                As[buf][c4 + 3][r] = ra[i].w;
            }
        }
        #pragma unroll
        for (int i = 0; i < 2; i++)
            *(float4*)&Bs[buf][br + i * 8][bc4] = rb[i];
    };

    float acc[10][8];
    #pragma unroll
    for (int i = 0; i < 10; i++)
        #pragma unroll
        for (int j = 0; j < 8; j++) acc[i][j] = 0.0f;

    ldg(0);
    sts(0);
    __syncthreads();

    int buf = 0;
    for (int k0 = 16; k0 <= K; k0 += 16) {
        if (k0 < K) ldg(k0);
        #pragma unroll
        for (int k = 0; k < 16; k++) {
            float a[10], b[8];
            #pragma unroll
            for (int j = 0; j < 5; j++)
                *(float2*)&a[j * 2] = *(const float2*)&As[buf][k][ty * 10 + j * 2];
            *(float4*)&b[0] = *(const float4*)&Bs[buf][k][tx * 8];
            *(float4*)&b[4] = *(const float4*)&Bs[buf][k][tx * 8 + 4];
            #pragma unroll
            for (int i = 0; i < 10; i++)
                #pragma unroll
                for (int j = 0; j < 8; j++)
                    acc[i][j] = fmaf(a[i], b[j], acc[i][j]);
        }
        if (k0 < K) sts(buf ^ 1);
        __syncthreads();
        buf ^= 1;
    }

    // epilogue: scale by dinv[row], write g_y
    #pragma unroll
    for (int i = 0; i < 10; i++) {
        int gr = rowBase + ty * 10 + i;
        if (gr >= M) continue;
        float s = g_dinv[gr];
        #pragma unroll
        for (int j = 0; j < 8; j += 4) {
            float4 v;
            v.x = acc[i][j + 0] * s;
            v.y = acc[i][j + 1] * s;
            v.z = acc[i][j + 2] * s;
            v.w = acc[i][j + 3] * s;
            *(float4*)&g_y[(size_t)gr * DH + colBase + tx * 8 + j] = v;
        }
    }
}

// ---------------- CSR gather: acc = y[node] + sum(y[src]); h = relu(acc*dinv + b)
// 64 threads (float4 each) per node, 4 nodes per 256-thread block.
// LAYER2: fuse mean-pool accumulation instead of writing g_h.
template<bool LAYER2>
__global__ void __launch_bounds__(256)
k_gather(const int* __restrict__ batch, const float* __restrict__ bias, int N)
{
    int node = blockIdx.x * 4 + (threadIdx.x >> 6);
    if (node >= N) return;
    int c = (threadIdx.x & 63) << 2;

    float4 acc = *(const float4*)(g_y + (size_t)node * DH + c);  // self loop
    const int beg = g_off[node];
    const int cnt = (int)g_deg[node] - 1;
    #pragma unroll 4
    for (int j = 0; j < cnt; j++) {
        int s = g_esrc[beg + j];
        float4 v = *(const float4*)(g_y + (size_t)s * DH + c);
        acc.x += v.x; acc.y += v.y; acc.z += v.z; acc.w += v.w;
    }

    float dv = g_dinv[node];
    float4 b = *(const float4*)(bias + c);
    float4 r;
    r.x = fmaxf(fmaf(acc.x, dv, b.x), 0.f);
    r.y = fmaxf(fmaf(acc.y, dv, b.y), 0.f);
    r.z = fmaxf(fmaf(acc.z, dv, b.z), 0.f);
    r.w = fmaxf(fmaf(acc.w, dv, b.w), 0.f);

    if (!LAYER2) {
        *(float4*)(g_h + (size_t)node * DH + c) = r;
    } else {
        int g = batch[node];
        float* o = g_pool + (size_t)g * DH + c;
        atomicAdd(o + 0, r.x);
        atomicAdd(o + 1, r.y);
        atomicAdd(o + 2, r.z);
        atomicAdd(o + 3, r.w);
    }
}

// ---------------- final FC ----------------
__global__ void k_fc(const float* __restrict__ wfc, const float* __restrict__ bfc,
                     float* __restrict__ out)
{
    int w = (blockIdx.x * blockDim.x + threadIdx.x) >> 5;
    int lane = threadIdx.x & 31;
    if (w >= GNUM) return;
    float sum = 0.f;
    #pragma unroll
    for (int j = lane; j < DH; j += 32)
        sum += g_pool[w * DH + j] * wfc[j];
    #pragma unroll
    for (int o = 16; o; o >>= 1)
        sum += __shfl_xor_sync(0xffffffffu, sum, o);
    if (lane == 0)
        out[w] = sum / fmaxf(g_cnt[w], 1.f) + bfc[0];
}

// ---------------- launch ----------------
extern "C" void kernel_launch(void* const* d_in, const int* in_sizes, int n_in,
                              void* d_out, int out_size)
{
    const float* x     = (const float*)d_in[0];
    const int*   ei    = (const int*)  d_in[1];
    const int*   batch = (const int*)  d_in[2];
    const float* W1    = (const float*)d_in[3];
    const float* b1    = (const float*)d_in[4];
    const float* W2    = (const float*)d_in[5];
    const float* b2    = (const float*)d_in[6];
    const float* wfc   = (const float*)d_in[7];
    const float* bfc   = (const float*)d_in[8];
    float* out = (float*)d_out;

    const int N = in_sizes[2];        // 20000
    const int E = in_sizes[1] / 2;    // 320000
    const int* src = ei;
    const int* dst = ei + E;

    const int nblk = (N + 127) / 128;

    // prep: degree, dinv, group counts, CSR (hierarchical scan)
    k_init_misc<<<(GNUM * DH + NMAX + 255) / 256, 256>>>();
    k_deg_acc  <<<(E + 255) / 256, 256>>>(dst, E);
    k_dinv_cnt <<<(N + 255) / 256, 256>>>(batch, N);
    k_scan_part<<<nblk, 128>>>(N);
    k_scan_tops<<<1, 256>>>(nblk);
    k_scan_off <<<nblk, 128>>>(N);
    k_fill     <<<(E + 255) / 256, 256>>>(src, dst, E);

    dim3 gemm_grid((N + 159) / 160, DH / 128);
    int  gat_blocks = (N + 3) / 4;

    // layer 1
    k_gemm<DIN, false><<<gemm_grid, 256>>>(x, W1, N);
    k_gather<false><<<gat_blocks, 256>>>(batch, b1, N);

    // layer 2
    k_gemm<DH, true><<<gemm_grid, 256>>>(x /*unused*/, W2, N);
    k_gather<true><<<gat_blocks, 256>>>(batch, b2, N);

    // fc
    k_fc<<<GNUM * 32 / 128, 128>>>(wfc, bfc, out);
}

// round 5
// speedup vs baseline: 3.5739x; 1.4266x over previous
#include <cuda_runtime.h>
#include <cstdint>

#define DIN 512
#define DH  256
#define GNUM 128
#define NMAX 20000
#define EMAX 320000
#define NBLK_MAX 256

// ---- scratch (static __device__ globals; no allocation allowed) ----
__device__ float g_y[NMAX * DH];
__device__ float g_h[NMAX * DH];
__device__ float g_deg[NMAX];
__device__ float g_dinv[NMAX];
__device__ int   g_off[NMAX];
__device__ int   g_cursor[NMAX];
__device__ int   g_esrc[EMAX];
__device__ int   g_bsum[NBLK_MAX];
__device__ int   g_bpre[NBLK_MAX];
__device__ float g_pool[GNUM * DH];
__device__ float g_cnt[GNUM];

// ================= helpers =================
__device__ __forceinline__ float tf32r(float x) {
    uint32_t u;
    asm("cvt.rna.tf32.f32 %0, %1;" : "=r"(u) : "f"(x));
    return __uint_as_float(u);
}

__device__ __forceinline__ void mma_tf32(float* c, const uint32_t* a, const uint32_t* b) {
    asm volatile("mma.sync.aligned.m16n8k8.row.col.f32.tf32.tf32.f32 "
        "{%0,%1,%2,%3}, {%4,%5,%6,%7}, {%8,%9}, {%0,%1,%2,%3};"
        : "+f"(c[0]), "+f"(c[1]), "+f"(c[2]), "+f"(c[3])
        : "r"(a[0]), "r"(a[1]), "r"(a[2]), "r"(a[3]), "r"(b[0]), "r"(b[1]));
}

// ================= init / degree / dinv =================
__global__ void k_init_misc() {
    int t = blockIdx.x * blockDim.x + threadIdx.x;
    if (t < GNUM * DH) g_pool[t] = 0.f;
    if (t < GNUM) g_cnt[t] = 0.f;
    if (t < NMAX) g_deg[t] = 1.0f;
}

__global__ void k_deg_acc(const int* __restrict__ dst, int E) {
    int e = blockIdx.x * blockDim.x + threadIdx.x;
    if (e < E) atomicAdd(&g_deg[dst[e]], 1.0f);
}

__global__ void k_dinv_cnt(const int* __restrict__ batch, int N) {
    int i = blockIdx.x * blockDim.x + threadIdx.x;
    if (i < N) {
        g_dinv[i] = rsqrtf(g_deg[i]);
        atomicAdd(&g_cnt[batch[i]], 1.0f);
    }
}

// ================= hierarchical scan =================
__global__ void __launch_bounds__(128) k_scan_part(int N) {
    __shared__ int ws[4];
    int i = blockIdx.x * 128 + threadIdx.x;
    int v = (i < N) ? (int)g_deg[i] - 1 : 0;
    int s = v;
    #pragma unroll
    for (int o = 16; o; o >>= 1) s += __shfl_xor_sync(0xffffffffu, s, o);
    if ((threadIdx.x & 31) == 0) ws[threadIdx.x >> 5] = s;
    __syncthreads();
    if (threadIdx.x == 0) g_bsum[blockIdx.x] = ws[0] + ws[1] + ws[2] + ws[3];
}

__global__ void __launch_bounds__(256) k_scan_tops(int nblk) {
    __shared__ int ws[8];
    int tid = threadIdx.x;
    int v = (tid < nblk) ? g_bsum[tid] : 0;
    int lane = tid & 31, w = tid >> 5;
    int inc = v;
    #pragma unroll
    for (int o = 1; o < 32; o <<= 1) {
        int t = __shfl_up_sync(0xffffffffu, inc, o);
        if (lane >= o) inc += t;
    }
    if (lane == 31) ws[w] = inc;
    __syncthreads();
    if (w == 0 && lane < 8) {
        int x = ws[lane];
        #pragma unroll
        for (int o = 1; o < 8; o <<= 1) {
            int t = __shfl_up_sync(0xffu, x, o);
            if (lane >= o) x += t;
        }
        ws[lane] = x;
    }
    __syncthreads();
    int excl = inc - v + (w ? ws[w - 1] : 0);
    if (tid < nblk) g_bpre[tid] = excl;
}

__global__ void __launch_bounds__(128) k_scan_off(int N) {
    __shared__ int ws[4];
    int i = blockIdx.x * 128 + threadIdx.x;
    int v = (i < N) ? (int)g_deg[i] - 1 : 0;
    int lane = threadIdx.x & 31, w = threadIdx.x >> 5;
    int inc = v;
    #pragma unroll
    for (int o = 1; o < 32; o <<= 1) {
        int t = __shfl_up_sync(0xffffffffu, inc, o);
        if (lane >= o) inc += t;
    }
    if (lane == 31) ws[w] = inc;
    __syncthreads();
    int base = g_bpre[blockIdx.x];
    if (w == 0 && lane < 4) {
        int x = ws[lane];
        #pragma unroll
        for (int o = 1; o < 4; o <<= 1) {
            int t = __shfl_up_sync(0xfu, x, o);
            if (lane >= o) x += t;
        }
        ws[lane] = x;
    }
    __syncthreads();
    if (i < N) {
        int excl = inc - v + (w ? ws[w - 1] : 0);
        g_off[i] = base + excl;
        g_cursor[i] = 0;
    }
}

__global__ void k_fill(const int* __restrict__ src, const int* __restrict__ dst, int E) {
    int e = blockIdx.x * blockDim.x + threadIdx.x;
    if (e >= E) return;
    int d = dst[e];
    int pos = g_off[d] + atomicAdd(&g_cursor[d], 1);
    g_esrc[pos] = src[e];
}

// ================= TF32 mma.sync GEMM: g_y = (A @ W) * dinv[row] =================
// CTA tile 160x128, BK=32, 10 warps (320 thr), warptile 32x64 (2x8 m16n8k8 tiles).
// Smem: As [160][36] (pad -> conflict-free frag lds), Bs [32][136], double buffered.
#define AST 36
#define BST 136
#define AS_F (160 * AST)            // 5760 floats per buffer
#define BS_F (32 * BST)             // 4352 floats per buffer
#define SMEM_GEMM_BYTES ((2 * AS_F + 2 * BS_F) * 4)   // 80896 B

template<int K, bool FROM_H>
__global__ void __launch_bounds__(320, 2)
k_gemm_mma(const float* __restrict__ Ax, const float* __restrict__ W, int M)
{
    extern __shared__ float sm[];
    const float* __restrict__ A = FROM_H ? (const float*)g_h : Ax;

    const int tid = threadIdx.x;
    const int wid = tid >> 5;
    const int lid = tid & 31;
    const int gid = lid >> 2;       // groupID 0..7
    const int tig = lid & 3;        // thread-in-group 0..3
    const int warpM = wid % 5;      // 0..4 -> 32-row slabs
    const int warpN = wid / 5;      // 0..1 -> 64-col slabs
    const int rowBase = blockIdx.x * 160;
    const int colBase = blockIdx.y * 128;
    constexpr int NC = K / 32;

    float C[2][8][4];
    #pragma unroll
    for (int mt = 0; mt < 2; mt++)
        #pragma unroll
        for (int nt = 0; nt < 8; nt++)
            #pragma unroll
            for (int i = 0; i < 4; i++) C[mt][nt][i] = 0.f;

    auto stage = [&](int buf, int c) {
        float* As = sm + buf * AS_F;
        float* Bs = sm + 2 * AS_F + buf * BS_F;
        // A chunk: 160 x 32 floats = 1280 float4, 320 thr x 4
        #pragma unroll
        for (int i = 0; i < 4; i++) {
            int idx = tid + i * 320;
            int m = idx >> 3, k4 = (idx & 7) << 2;
            int gr = rowBase + m;
            float4 v = make_float4(0.f, 0.f, 0.f, 0.f);
            if (gr < M) v = *(const float4*)(A + (size_t)gr * K + c * 32 + k4);
            v.x = tf32r(v.x); v.y = tf32r(v.y); v.z = tf32r(v.z); v.w = tf32r(v.w);
            *(float4*)&As[m * AST + k4] = v;
        }
        // B chunk: 32 x 128 floats = 1024 float4
        #pragma unroll
        for (int i = 0; i < 4; i++) {
            int idx = tid + i * 320;
            if (idx < 1024) {
                int k = idx >> 5, n4 = (idx & 31) << 2;
                float4 v = *(const float4*)(W + (size_t)(c * 32 + k) * DH + colBase + n4);
                v.x = tf32r(v.x); v.y = tf32r(v.y); v.z = tf32r(v.z); v.w = tf32r(v.w);
                *(float4*)&Bs[k * BST + n4] = v;
            }
        }
    };

    stage(0, 0);

    for (int c = 0; c < NC; c++) {
        __syncthreads();
        if (c + 1 < NC) stage((c + 1) & 1, c + 1);

        const int buf = c & 1;
        const float* As = sm + buf * AS_F;
        const float* Bs = sm + 2 * AS_F + buf * BS_F;

        #pragma unroll
        for (int ks = 0; ks < 4; ks++) {
            const int kk = ks * 8 + tig;
            uint32_t a[2][4];
            #pragma unroll
            for (int mt = 0; mt < 2; mt++) {
                int mr = warpM * 32 + mt * 16 + gid;
                a[mt][0] = __float_as_uint(As[mr * AST + kk]);
                a[mt][1] = __float_as_uint(As[(mr + 8) * AST + kk]);
                a[mt][2] = __float_as_uint(As[mr * AST + kk + 4]);
                a[mt][3] = __float_as_uint(As[(mr + 8) * AST + kk + 4]);
            }
            #pragma unroll
            for (int nt = 0; nt < 8; nt++) {
                int nc = warpN * 64 + nt * 8 + gid;
                uint32_t b[2];
                b[0] = __float_as_uint(Bs[kk * BST + nc]);
                b[1] = __float_as_uint(Bs[(kk + 4) * BST + nc]);
                mma_tf32(C[0][nt], a[0], b);
                mma_tf32(C[1][nt], a[1], b);
            }
        }
    }

    // epilogue: scale by dinv[row], write g_y (float2 per fragment pair)
    #pragma unroll
    for (int mt = 0; mt < 2; mt++) {
        int gr0 = rowBase + warpM * 32 + mt * 16 + gid;
        int gr1 = gr0 + 8;
        float d0 = (gr0 < M) ? g_dinv[gr0] : 0.f;
        float d1 = (gr1 < M) ? g_dinv[gr1] : 0.f;
        #pragma unroll
        for (int nt = 0; nt < 8; nt++) {
            int col = colBase + warpN * 64 + nt * 8 + tig * 2;
            if (gr0 < M) {
                float2 v = make_float2(C[mt][nt][0] * d0, C[mt][nt][1] * d0);
                *(float2*)&g_y[(size_t)gr0 * DH + col] = v;
            }
            if (gr1 < M) {
                float2 v = make_float2(C[mt][nt][2] * d1, C[mt][nt][3] * d1);
                *(float2*)&g_y[(size_t)gr1 * DH + col] = v;
            }
        }
    }
}

// ================= CSR gather =================
template<bool LAYER2>
__global__ void __launch_bounds__(256)
k_gather(const int* __restrict__ batch, const float* __restrict__ bias, int N)
{
    int node = blockIdx.x * 4 + (threadIdx.x >> 6);
    if (node >= N) return;
    int c = (threadIdx.x & 63) << 2;

    float4 acc = *(const float4*)(g_y + (size_t)node * DH + c);
    const int beg = g_off[node];
    const int cnt = (int)g_deg[node] - 1;
    #pragma unroll 4
    for (int j = 0; j < cnt; j++) {
        int s = g_esrc[beg + j];
        float4 v = *(const float4*)(g_y + (size_t)s * DH + c);
        acc.x += v.x; acc.y += v.y; acc.z += v.z; acc.w += v.w;
    }

    float dv = g_dinv[node];
    float4 b = *(const float4*)(bias + c);
    float4 r;
    r.x = fmaxf(fmaf(acc.x, dv, b.x), 0.f);
    r.y = fmaxf(fmaf(acc.y, dv, b.y), 0.f);
    r.z = fmaxf(fmaf(acc.z, dv, b.z), 0.f);
    r.w = fmaxf(fmaf(acc.w, dv, b.w), 0.f);

    if (!LAYER2) {
        *(float4*)(g_h + (size_t)node * DH + c) = r;
    } else {
        int g = batch[node];
        float* o = g_pool + (size_t)g * DH + c;
        atomicAdd(o + 0, r.x);
        atomicAdd(o + 1, r.y);
        atomicAdd(o + 2, r.z);
        atomicAdd(o + 3, r.w);
    }
}

// ================= final FC =================
__global__ void k_fc(const float* __restrict__ wfc, const float* __restrict__ bfc,
                     float* __restrict__ out)
{
    int w = (blockIdx.x * blockDim.x + threadIdx.x) >> 5;
    int lane = threadIdx.x & 31;
    if (w >= GNUM) return;
    float sum = 0.f;
    #pragma unroll
    for (int j = lane; j < DH; j += 32)
        sum += g_pool[w * DH + j] * wfc[j];
    #pragma unroll
    for (int o = 16; o; o >>= 1)
        sum += __shfl_xor_sync(0xffffffffu, sum, o);
    if (lane == 0)
        out[w] = sum / fmaxf(g_cnt[w], 1.f) + bfc[0];
}

// ================= launch =================
extern "C" void kernel_launch(void* const* d_in, const int* in_sizes, int n_in,
                              void* d_out, int out_size)
{
    const float* x     = (const float*)d_in[0];
    const int*   ei    = (const int*)  d_in[1];
    const int*   batch = (const int*)  d_in[2];
    const float* W1    = (const float*)d_in[3];
    const float* b1    = (const float*)d_in[4];
    const float* W2    = (const float*)d_in[5];
    const float* b2    = (const float*)d_in[6];
    const float* wfc   = (const float*)d_in[7];
    const float* bfc   = (const float*)d_in[8];
    float* out = (float*)d_out;

    const int N = in_sizes[2];        // 20000
    const int E = in_sizes[1] / 2;    // 320000
    const int* src = ei;
    const int* dst = ei + E;
    const int nblk = (N + 127) / 128;

    cudaFuncSetAttribute(k_gemm_mma<DIN, false>,
                         cudaFuncAttributeMaxDynamicSharedMemorySize, SMEM_GEMM_BYTES);
    cudaFuncSetAttribute(k_gemm_mma<DH, true>,
                         cudaFuncAttributeMaxDynamicSharedMemorySize, SMEM_GEMM_BYTES);

    // prep
    k_init_misc<<<(GNUM * DH + NMAX + 255) / 256, 256>>>();
    k_deg_acc  <<<(E + 255) / 256, 256>>>(dst, E);
    k_dinv_cnt <<<(N + 255) / 256, 256>>>(batch, N);
    k_scan_part<<<nblk, 128>>>(N);
    k_scan_tops<<<1, 256>>>(nblk);
    k_scan_off <<<nblk, 128>>>(N);
    k_fill     <<<(E + 255) / 256, 256>>>(src, dst, E);

    dim3 gemm_grid((N + 159) / 160, DH / 128);
    const int gat_blocks = (N + 3) / 4;

    // layer 1
    k_gemm_mma<DIN, false><<<gemm_grid, 320, SMEM_GEMM_BYTES>>>(x, W1, N);
    k_gather<false><<<gat_blocks, 256>>>(batch, b1, N);

    // layer 2
    k_gemm_mma<DH, true><<<gemm_grid, 320, SMEM_GEMM_BYTES>>>(x /*unused*/, W2, N);
    k_gather<true><<<gat_blocks, 256>>>(batch, b2, N);

    // fc
    k_fc<<<GNUM * 32 / 128, 128>>>(wfc, bfc, out);
}